// round 15
// baseline (speedup 1.0000x reference)
#include <cuda_runtime.h>
#include <cstdint>

// Problem constants
#define Bc 64
#define Cc 256
#define Hc 28
#define Wc 28
#define Nc 784            // H*W
#define CH 32             // channel chunk
#define NCHUNK (Cc / CH)  // 8
#define BROWS 4           // FIXED z band rows (compile-time; provable superset)
#define BN (BROWS * Wc)   // 112
#define NQZ (BN / 4)      // 28 (compile-time)
#define MAXP 512          // max pairs per block (provable <= ~400)
#define ZOFF1 (CH * BN + 4)
#define NBLK (Hc * Bc)    // 1792 blocks

__device__ double g_part[2 * NBLK];
__device__ int    g_pcnt[2 * NBLK];
__device__ unsigned int g_done = 0;

__device__ __forceinline__ void cp_async16(unsigned int smem_addr, const void* gptr) {
    asm volatile("cp.async.cg.shared.global [%0], [%1], 16;\n" :: "r"(smem_addr), "l"(gptr));
}
__device__ __forceinline__ void cp_async_commit_wait() {
    asm volatile("cp.async.commit_group;\n" ::: "memory");
    asm volatile("cp.async.wait_group 0;\n" ::: "memory");
}

__global__ __launch_bounds__(256, 5) void cl_main_kernel(
    const float* __restrict__ y1, const float* __restrict__ y2,
    const float* __restrict__ z1, const float* __restrict__ z2,
    const float* __restrict__ g1, const float* __restrict__ g2,
    float* __restrict__ out)
{
    __shared__ float ysm[2 * CH * Wc];       // [view][c][nl]
    __shared__ float zsm[2 * CH * BN + 4];   // [view][c][j], view1 at +ZOFF1
    __shared__ float yn2[2][Wc];
    __shared__ float zn2[2][BN];
    __shared__ float s_g1x[Wc];
    __shared__ float s_g2y[BN];
    __shared__ float s_g2x[BN];
    __shared__ int   s_pairs[MAXP];          // (view<<16)|(nl<<8)|j
    __shared__ int   s_np;
    __shared__ int   s_r0;
    __shared__ float s_bin1, s_bin2, s_g1y;
    __shared__ int   s_last;
    __shared__ double red_s0[8], red_s1[8], red_c0[8], red_c1[8];

    const int yr = blockIdx.x;  // grid1 row 0..27
    const int b  = blockIdx.y;  // batch
    const int t  = threadIdx.x;
    const int blk = b * Hc + yr;

    const float* g1b = g1 + (size_t)b * 2 * Nc;
    const float* g2b = g2 + (size_t)b * 2 * Nc;

    if (t == 0) {
        float d1y = g1b[29] - g1b[0];
        float d1x = g1b[Nc + 29] - g1b[Nc + 0];
        float bin1 = __fsqrt_rn(__fadd_rn(__fmul_rn(d1y, d1y), __fmul_rn(d1x, d1x)));
        float d2y = g2b[29] - g2b[0];
        float d2x = g2b[Nc + 29] - g2b[Nc + 0];
        float bin2 = __fsqrt_rn(__fadd_rn(__fmul_rn(d2y, d2y), __fmul_rn(d2x, d2x)));
        s_bin1 = bin1; s_bin2 = bin2;
        float g1y = g1b[yr * Wc];
        s_g1y = g1y;
        // any row with an exact-mask pair satisfies |gy - g1y| <= 0.7*max(bin) < thrm,
        // and such rows form a contiguous run of <= 3 rows -> 4-row window is a superset.
        float thrm = 0.7f * fmaxf(bin1, bin2) * 1.0002f + 1e-3f;
        int r0 = -1;
        for (int my = 0; my < Hc; my++) {
            float gy = g2b[my * Wc];
            if (fabsf(gy - g1y) <= thrm) { r0 = my; break; }
        }
        if (r0 > Hc - BROWS) r0 = Hc - BROWS;
        s_r0 = r0;
        s_np = 0;
    }
    __syncthreads();

    double acc0 = 0.0, acc1 = 0.0;   // per-thread sims
    int    cnt0 = 0,  cnt1 = 0;

    const int r0 = s_r0;
    if (r0 >= 0) {                      // ---- active path ----
        const int m0 = r0 * Wc;
        const int nbase = yr * Wc;

        // stage grid coords + zero norms (all constant bounds)
        if (t < Wc) s_g1x[t] = g1b[Nc + nbase + t];
        if (t < BN) { s_g2y[t] = g2b[m0 + t]; s_g2x[t] = g2b[Nc + m0 + t]; }
        if (t < 2 * Wc) yn2[t / Wc][t % Wc] = 0.f;
        if (t < 2 * BN - 32) { }        // (covered by loop below)
        for (int j = t; j < 2 * BN; j += 256) zn2[j / BN][j % BN] = 0.f;
        __syncthreads();

        // ---- exact mask evaluation (bit-matches reference float ops) ----
        const float bin1 = s_bin1, bin2 = s_bin2, g1y = s_g1y;
        #pragma unroll 1
        for (int idx = t; idx < Wc * BN; idx += 256) {
            int nl = idx / BN;          // constant divisor -> mul-shift
            int j  = idx - nl * BN;
            float dy = g1y - s_g2y[j];
            float dx = s_g1x[nl] - s_g2x[j];
            float dist = __fsqrt_rn(__fadd_rn(__fmul_rn(dy, dy), __fmul_rn(dx, dx)));
            bool m1 = (__fdiv_rn(dist, bin1) <= 0.7f);
            bool m2 = (__fdiv_rn(dist, bin2) <= 0.7f);
            if (m1) { int p = atomicAdd(&s_np, 1); if (p < MAXP) s_pairs[p] = (0 << 16) | (nl << 8) | j; }
            if (m2) { int p = atomicAdd(&s_np, 1); if (p < MAXP) s_pairs[p] = (1 << 16) | (nl << 8) | j; }
        }
        __syncthreads();
        int np = s_np; if (np > MAXP) np = MAXP;

        // view 0: y1 vs z2 ; view 1: y2 vs z1
        const float* ya[2] = { y1 + (size_t)b * Cc * Nc, y2 + (size_t)b * Cc * Nc };
        const float* za[2] = { z2 + (size_t)b * Cc * Nc, z1 + (size_t)b * Cc * Nc };

        unsigned int ysm0 = (unsigned int)__cvta_generic_to_shared(ysm);
        unsigned int zsm0 = (unsigned int)__cvta_generic_to_shared(zsm);

        float dacc[2] = {0.f, 0.f};

        // ---- chunk loop (all divisors compile-time) ----
        #pragma unroll 1
        for (int ci = 0; ci < NCHUNK; ci++) {
            const int cc = ci * CH;
            __syncthreads();   // previous chunk's readers done before refill
            #pragma unroll 1
            for (int e = t; e < 2 * CH * (Wc / 4); e += 256) {     // 448 ops
                int v  = e / (CH * (Wc / 4));
                int r  = e - v * (CH * (Wc / 4));
                int cl = r / (Wc / 4);
                int q  = r - cl * (Wc / 4);
                unsigned int saddr = ysm0 + (unsigned int)(((v * CH + cl) * Wc + (q << 2)) * 4);
                cp_async16(saddr, ya[v] + (size_t)(cc + cl) * Nc + nbase + (q << 2));
            }
            #pragma unroll 1
            for (int e = t; e < 2 * CH * NQZ; e += 256) {          // 1792 ops
                int v  = e / (CH * NQZ);
                int r  = e - v * (CH * NQZ);
                int cl = r / NQZ;
                int q  = r - cl * NQZ;
                unsigned int saddr = zsm0 + (unsigned int)((v * ZOFF1 + cl * BN + (q << 2)) * 4);
                cp_async16(saddr, za[v] + (size_t)(cc + cl) * Nc + m0 + (q << 2));
            }
            cp_async_commit_wait();
            __syncthreads();

            // column norms^2 (constant bounds; lanes take consecutive cols)
            if (t < 2 * Wc) {
                int v = t / Wc, nl = t - v * Wc;
                const float* yv = ysm + v * CH * Wc;
                float s = 0.f;
                #pragma unroll
                for (int cl = 0; cl < CH; cl++) { float x = yv[cl * Wc + nl]; s += x * x; }
                yn2[v][nl] += s;
            }
            if (t < 2 * BN) {
                int v = t / BN, j = t - v * BN;
                const float* zv = zsm + v * ZOFF1;
                float s = 0.f;
                #pragma unroll
                for (int cl = 0; cl < CH; cl++) { float x = zv[cl * BN + j]; s += x * x; }
                zn2[v][j] += s;
            }

            // balanced pair dots (all threads, <=2 pairs each)
            #pragma unroll 1
            for (int p = t, k = 0; p < np; p += 256, k++) {
                int pr = s_pairs[p];
                int v = pr >> 16, nl = (pr >> 8) & 255, j = pr & 255;
                const float* yv = ysm + v * CH * Wc + nl;
                const float* zv = zsm + v * ZOFF1 + j;
                float s = 0.f;
                #pragma unroll
                for (int cl = 0; cl < CH; cl++) s = fmaf(yv[cl * Wc], zv[cl * BN], s);
                dacc[k] += s;
            }
        }
        __syncthreads();

        // ---- per-pair cosine sims ----
        #pragma unroll 1
        for (int p = t, k = 0; p < np; p += 256, k++) {
            int pr = s_pairs[p];
            int v = pr >> 16, nl = (pr >> 8) & 255, j = pr & 255;
            float den = fmaxf(__fsqrt_rn(yn2[v][nl] * zn2[v][j]), 1e-8f);
            float sim = dacc[k] / den;
            if (v == 0) { acc0 += (double)sim; cnt0++; }
            else        { acc1 += (double)sim; cnt1++; }
        }
    }

    // ---- block reduction of sims ----
    for (int off = 16; off; off >>= 1) {
        acc0 += __shfl_down_sync(0xffffffffu, acc0, off);
        acc1 += __shfl_down_sync(0xffffffffu, acc1, off);
        cnt0 += __shfl_down_sync(0xffffffffu, cnt0, off);
        cnt1 += __shfl_down_sync(0xffffffffu, cnt1, off);
    }
    int wid = t >> 5, lane = t & 31;
    if (lane == 0) { red_s0[wid] = acc0; red_s1[wid] = acc1; red_c0[wid] = (double)cnt0; red_c1[wid] = (double)cnt1; }
    __syncthreads();

    // ---- publish per-block partials + last-block finalize ----
    if (t == 0) {
        double S0 = 0, S1 = 0, C0 = 0, C1 = 0;
        #pragma unroll
        for (int w = 0; w < 8; w++) { S0 += red_s0[w]; S1 += red_s1[w]; C0 += red_c0[w]; C1 += red_c1[w]; }
        g_part[blk]        = S0;
        g_part[NBLK + blk] = S1;
        g_pcnt[blk]        = (int)C0;
        g_pcnt[NBLK + blk] = (int)C1;
        __threadfence();
        unsigned int old = atomicAdd(&g_done, 1u);
        s_last = (old == (unsigned int)(NBLK - 1)) ? 1 : 0;
    }
    __syncthreads();

    if (s_last) {
        __threadfence();   // acquire: all blocks' partials visible
        double s0 = 0.0, s1 = 0.0, c0 = 0.0, c1 = 0.0;
        for (int i = t; i < NBLK; i += 256) {
            s0 += g_part[i]; s1 += g_part[NBLK + i];
            c0 += (double)g_pcnt[i]; c1 += (double)g_pcnt[NBLK + i];
        }
        for (int off = 16; off; off >>= 1) {
            s0 += __shfl_down_sync(0xffffffffu, s0, off);
            s1 += __shfl_down_sync(0xffffffffu, s1, off);
            c0 += __shfl_down_sync(0xffffffffu, c0, off);
            c1 += __shfl_down_sync(0xffffffffu, c1, off);
        }
        if (lane == 0) { red_s0[wid] = s0; red_s1[wid] = s1; red_c0[wid] = c0; red_c1[wid] = c1; }
        __syncthreads();
        if (t == 0) {
            double S0 = 0, S1 = 0, C0 = 0, C1 = 0;
            #pragma unroll
            for (int w = 0; w < 8; w++) { S0 += red_s0[w]; S1 += red_s1[w]; C0 += red_c0[w]; C1 += red_c1[w]; }
            double l0 = (C0 > 0.0) ? S0 / C0 : 0.0;
            double l1 = (C1 > 0.0) ? S1 / C1 : 0.0;
            out[0] = (float)(-(l0 + l1));
            g_done = 0;   // reset for next (graph-replayed) call — deterministic
        }
    }
}

extern "C" void kernel_launch(void* const* d_in, const int* in_sizes, int n_in,
                              void* d_out, int out_size) {
    (void)in_sizes; (void)n_in; (void)out_size;
    const float* y1 = (const float*)d_in[0];
    const float* y2 = (const float*)d_in[1];
    const float* z1 = (const float*)d_in[2];
    const float* z2 = (const float*)d_in[3];
    const float* g1 = (const float*)d_in[4];
    const float* g2 = (const float*)d_in[5];

    dim3 grid(Hc, Bc);
    cl_main_kernel<<<grid, 256>>>(y1, y2, z1, z2, g1, g2, (float*)d_out);
}

// round 16
// speedup vs baseline: 1.0431x; 1.0431x over previous
#include <cuda_runtime.h>
#include <cstdint>

// Problem constants
#define Bc 64
#define Cc 256
#define Hc 28
#define Wc 28
#define Nc 784            // H*W
#define CH 16             // channel chunk
#define NCHUNK (Cc / CH)  // 16
#define BROWS 4           // max grid2 band rows (provable <= 4)
#define BN (BROWS * Wc)   // 112
#define MAXP 512          // max pairs per block (provable <= ~400)
#define ZOFF1 (CH * BN + 4)
#define NBLK (Hc * Bc)    // 1792 blocks

__device__ double g_part[2 * NBLK];
__device__ int    g_pcnt[2 * NBLK];

__device__ __forceinline__ void cp_async16(unsigned int smem_addr, const void* gptr) {
    asm volatile("cp.async.cg.shared.global [%0], [%1], 16;\n" :: "r"(smem_addr), "l"(gptr));
}
__device__ __forceinline__ void cp_async_commit_wait() {
    asm volatile("cp.async.commit_group;\n" ::: "memory");
    asm volatile("cp.async.wait_group 0;\n" ::: "memory");
}

__global__ __launch_bounds__(256, 7) void cl_main_kernel(
    const float* __restrict__ y1, const float* __restrict__ y2,
    const float* __restrict__ z1, const float* __restrict__ z2,
    const float* __restrict__ g1, const float* __restrict__ g2)
{
    __shared__ float ysm[2 * CH * Wc];       // [view][c][nl]
    __shared__ float zsm[2 * CH * BN + 4];   // [view][c][j], view1 at +ZOFF1
    __shared__ float yn2[2][Wc];
    __shared__ float zn2[2][BN];
    __shared__ float s_g1x[Wc];
    __shared__ float s_g2y[BN];
    __shared__ float s_g2x[BN];
    __shared__ int   s_pairs[MAXP];          // (view<<16)|(nl<<8)|j
    __shared__ int   s_np;
    __shared__ int   s_r0, s_nb;
    __shared__ float s_bin1, s_bin2, s_g1y;
    __shared__ double red_s0[8], red_s1[8], red_c0[8], red_c1[8];

    const int yr = blockIdx.x;  // grid1 row 0..27
    const int b  = blockIdx.y;  // batch
    const int t  = threadIdx.x;
    const int blk = b * Hc + yr;

    const float* g1b = g1 + (size_t)b * 2 * Nc;
    const float* g2b = g2 + (size_t)b * 2 * Nc;

    if (t == 0) {
        float d1y = g1b[29] - g1b[0];
        float d1x = g1b[Nc + 29] - g1b[Nc + 0];
        float bin1 = __fsqrt_rn(__fadd_rn(__fmul_rn(d1y, d1y), __fmul_rn(d1x, d1x)));
        float d2y = g2b[29] - g2b[0];
        float d2x = g2b[Nc + 29] - g2b[Nc + 0];
        float bin2 = __fsqrt_rn(__fadd_rn(__fmul_rn(d2y, d2y), __fmul_rn(d2x, d2x)));
        s_bin1 = bin1; s_bin2 = bin2;
        float g1y = g1b[yr * Wc];
        s_g1y = g1y;
        float thrm = 0.7f * fmaxf(bin1, bin2) * 1.0002f + 1e-3f;
        int r0 = -1, r1 = -2;
        for (int my = 0; my < Hc; my++) {
            float gy = g2b[my * Wc];
            if (fabsf(gy - g1y) <= thrm) { if (r0 < 0) r0 = my; r1 = my; }
        }
        int nb = r1 - r0 + 1;
        if (nb < 0) nb = 0;
        if (nb > BROWS) nb = BROWS;
        s_r0 = r0; s_nb = nb;
        s_np = 0;
    }
    __syncthreads();

    double acc0 = 0.0, acc1 = 0.0;   // per-thread sims
    int    cnt0 = 0,  cnt1 = 0;

    const int nb = s_nb;
    if (nb > 0) {                       // ---- active path ----
        const int r0 = s_r0;
        const int m0 = r0 * Wc;
        const int bandn = nb * Wc;      // <= 112, multiple of 28
        const int nqz = bandn >> 2;
        const int nbase = yr * Wc;

        // stage grid coords + zero norms
        if (t < Wc) s_g1x[t] = g1b[Nc + nbase + t];
        for (int j = t; j < bandn; j += 256) {
            s_g2y[j] = g2b[m0 + j];
            s_g2x[j] = g2b[Nc + m0 + j];
        }
        if (t < 2 * Wc) yn2[t / Wc][t % Wc] = 0.f;
        for (int j = t; j < 2 * BN; j += 256) zn2[j / BN][j % BN] = 0.f;
        __syncthreads();

        // ---- exact mask evaluation (bit-matches reference float ops) ----
        const float bin1 = s_bin1, bin2 = s_bin2, g1y = s_g1y;
        for (int idx = t; idx < Wc * bandn; idx += 256) {
            int nl = idx / bandn;
            int j  = idx - nl * bandn;
            float dy = g1y - s_g2y[j];
            float dx = s_g1x[nl] - s_g2x[j];
            float dist = __fsqrt_rn(__fadd_rn(__fmul_rn(dy, dy), __fmul_rn(dx, dx)));
            bool m1 = (__fdiv_rn(dist, bin1) <= 0.7f);
            bool m2 = (__fdiv_rn(dist, bin2) <= 0.7f);
            if (m1) { int p = atomicAdd(&s_np, 1); if (p < MAXP) s_pairs[p] = (0 << 16) | (nl << 8) | j; }
            if (m2) { int p = atomicAdd(&s_np, 1); if (p < MAXP) s_pairs[p] = (1 << 16) | (nl << 8) | j; }
        }
        __syncthreads();
        int np = s_np; if (np > MAXP) np = MAXP;

        // view 0: y1 vs z2 ; view 1: y2 vs z1
        const float* ya[2] = { y1 + (size_t)b * Cc * Nc, y2 + (size_t)b * Cc * Nc };
        const float* za[2] = { z2 + (size_t)b * Cc * Nc, z1 + (size_t)b * Cc * Nc };

        unsigned int ysm0 = (unsigned int)__cvta_generic_to_shared(ysm);
        unsigned int zsm0 = (unsigned int)__cvta_generic_to_shared(zsm);

        float dacc[2] = {0.f, 0.f};

        // ---- chunk loop ----
        for (int ci = 0; ci < NCHUNK; ci++) {
            const int cc = ci * CH;
            __syncthreads();   // previous chunk's readers done before refill
            for (int e = t; e < 2 * CH * (Wc / 4); e += 256) {     // 224 ops
                int v  = e / (CH * (Wc / 4));
                int r  = e - v * (CH * (Wc / 4));
                int cl = r / (Wc / 4);
                int q  = r - cl * (Wc / 4);
                unsigned int saddr = ysm0 + (unsigned int)(((v * CH + cl) * Wc + (q << 2)) * 4);
                cp_async16(saddr, ya[v] + (size_t)(cc + cl) * Nc + nbase + (q << 2));
            }
            for (int e = t; e < 2 * CH * nqz; e += 256) {          // <=896 ops
                int v  = e / (CH * nqz);
                int r  = e - v * (CH * nqz);
                int cl = r / nqz;
                int q  = r - cl * nqz;
                unsigned int saddr = zsm0 + (unsigned int)((v * ZOFF1 + cl * BN + (q << 2)) * 4);
                cp_async16(saddr, za[v] + (size_t)(cc + cl) * Nc + m0 + (q << 2));
            }
            cp_async_commit_wait();
            __syncthreads();

            // column norms^2 (lanes: consecutive cols -> conflict-free)
            for (int col = t; col < 2 * Wc; col += 256) {
                int v = col / Wc, nl = col - v * Wc;
                const float* yv = ysm + v * CH * Wc;
                float s = 0.f;
                #pragma unroll
                for (int cl = 0; cl < CH; cl++) { float x = yv[cl * Wc + nl]; s += x * x; }
                yn2[v][nl] += s;
            }
            for (int col = t; col < 2 * bandn; col += 256) {
                int v = col / bandn, j = col - v * bandn;
                const float* zv = zsm + v * ZOFF1;
                float s = 0.f;
                #pragma unroll
                for (int cl = 0; cl < CH; cl++) { float x = zv[cl * BN + j]; s += x * x; }
                zn2[v][j] += s;
            }

            // balanced pair dots (all threads, <=2 pairs each)
            for (int p = t, k = 0; p < np; p += 256, k++) {
                int pr = s_pairs[p];
                int v = pr >> 16, nl = (pr >> 8) & 255, j = pr & 255;
                const float* yv = ysm + v * CH * Wc + nl;
                const float* zv = zsm + v * ZOFF1 + j;
                float s = 0.f;
                #pragma unroll
                for (int cl = 0; cl < CH; cl++) s = fmaf(yv[cl * Wc], zv[cl * BN], s);
                dacc[k] += s;
            }
        }
        __syncthreads();

        // ---- per-pair cosine sims ----
        for (int p = t, k = 0; p < np; p += 256, k++) {
            int pr = s_pairs[p];
            int v = pr >> 16, nl = (pr >> 8) & 255, j = pr & 255;
            float den = fmaxf(__fsqrt_rn(yn2[v][nl] * zn2[v][j]), 1e-8f);
            float sim = dacc[k] / den;
            if (v == 0) { acc0 += (double)sim; cnt0++; }
            else        { acc1 += (double)sim; cnt1++; }
        }
    }

    // ---- block reduction of sims ----
    for (int off = 16; off; off >>= 1) {
        acc0 += __shfl_down_sync(0xffffffffu, acc0, off);
        acc1 += __shfl_down_sync(0xffffffffu, acc1, off);
        cnt0 += __shfl_down_sync(0xffffffffu, cnt0, off);
        cnt1 += __shfl_down_sync(0xffffffffu, cnt1, off);
    }
    int wid = t >> 5, lane = t & 31;
    if (lane == 0) { red_s0[wid] = acc0; red_s1[wid] = acc1; red_c0[wid] = (double)cnt0; red_c1[wid] = (double)cnt1; }
    __syncthreads();

    // ---- publish per-block partials (no atomics, no init kernel needed) ----
    if (t == 0) {
        double S0 = 0, S1 = 0, C0 = 0, C1 = 0;
        #pragma unroll
        for (int w = 0; w < 8; w++) { S0 += red_s0[w]; S1 += red_s1[w]; C0 += red_c0[w]; C1 += red_c1[w]; }
        g_part[blk]        = S0;
        g_part[NBLK + blk] = S1;
        g_pcnt[blk]        = (int)C0;
        g_pcnt[NBLK + blk] = (int)C1;
    }
}

__global__ __launch_bounds__(256) void cl_fin_kernel(float* __restrict__ out) {
    __shared__ double rs0[8], rs1[8], rc0[8], rc1[8];
    int t = threadIdx.x;
    double s0 = 0.0, s1 = 0.0, c0 = 0.0, c1 = 0.0;
    for (int i = t; i < NBLK; i += 256) {
        s0 += g_part[i]; s1 += g_part[NBLK + i];
        c0 += (double)g_pcnt[i]; c1 += (double)g_pcnt[NBLK + i];
    }
    for (int off = 16; off; off >>= 1) {
        s0 += __shfl_down_sync(0xffffffffu, s0, off);
        s1 += __shfl_down_sync(0xffffffffu, s1, off);
        c0 += __shfl_down_sync(0xffffffffu, c0, off);
        c1 += __shfl_down_sync(0xffffffffu, c1, off);
    }
    int wid = t >> 5, lane = t & 31;
    if (lane == 0) { rs0[wid] = s0; rs1[wid] = s1; rc0[wid] = c0; rc1[wid] = c1; }
    __syncthreads();
    if (t == 0) {
        double S0 = 0, S1 = 0, C0 = 0, C1 = 0;
        #pragma unroll
        for (int w = 0; w < 8; w++) { S0 += rs0[w]; S1 += rs1[w]; C0 += rc0[w]; C1 += rc1[w]; }
        double l0 = (C0 > 0.0) ? S0 / C0 : 0.0;
        double l1 = (C1 > 0.0) ? S1 / C1 : 0.0;
        out[0] = (float)(-(l0 + l1));
    }
}

extern "C" void kernel_launch(void* const* d_in, const int* in_sizes, int n_in,
                              void* d_out, int out_size) {
    (void)in_sizes; (void)n_in; (void)out_size;
    const float* y1 = (const float*)d_in[0];
    const float* y2 = (const float*)d_in[1];
    const float* z1 = (const float*)d_in[2];
    const float* z2 = (const float*)d_in[3];
    const float* g1 = (const float*)d_in[4];
    const float* g2 = (const float*)d_in[5];

    dim3 grid(Hc, Bc);
    cl_main_kernel<<<grid, 256>>>(y1, y2, z1, z2, g1, g2);
    cl_fin_kernel<<<1, 256>>>((float*)d_out);
}

// round 17
// speedup vs baseline: 1.3573x; 1.3013x over previous
#include <cuda_runtime.h>
#include <cstdint>

// Problem constants
#define Bc 64
#define Cc 256
#define Hc 28
#define Wc 28
#define Nc 784            // H*W
#define CH 32             // channel chunk
#define NCHUNK (Cc / CH)  // 8
#define BROWS 3           // max grid2 band rows (provable <= 3: span 2*0.7*sqrt(2)*1.1 < 3*0.9)
#define BN (BROWS * Wc)   // 84
#define MAXP 512          // max pairs per block (provable <= ~400)
#define ZOFF1 (CH * BN + 4)

// zero-initialized at module load; fin resets after each replay -> deterministic
__device__ double g_sum[2];
__device__ unsigned long long g_cnt[2];

__device__ __forceinline__ void cp_async16(unsigned int smem_addr, const void* gptr) {
    asm volatile("cp.async.cg.shared.global [%0], [%1], 16;\n" :: "r"(smem_addr), "l"(gptr));
}
__device__ __forceinline__ void cp_async_commit_wait() {
    asm volatile("cp.async.commit_group;\n" ::: "memory");
    asm volatile("cp.async.wait_group 0;\n" ::: "memory");
}

__global__ __launch_bounds__(256, 6) void cl_main_kernel(
    const float* __restrict__ y1, const float* __restrict__ y2,
    const float* __restrict__ z1, const float* __restrict__ z2,
    const float* __restrict__ g1, const float* __restrict__ g2)
{
    __shared__ float ysm[2 * CH * Wc];       // [view][c][nl]
    __shared__ float zsm[2 * CH * BN + 4];   // [view][c][j], view1 at +ZOFF1
    __shared__ float yn2[2][Wc];
    __shared__ float zn2[2][BN];
    __shared__ float s_g1x[Wc];
    __shared__ float s_g2y[BN];
    __shared__ float s_g2x[BN];
    __shared__ int   s_pairs[MAXP];          // (view<<16)|(nl<<8)|j
    __shared__ int   s_np;
    __shared__ int   s_r0, s_nb;
    __shared__ float s_bin1, s_bin2, s_g1y;
    __shared__ double red_s0[8], red_s1[8], red_c0[8], red_c1[8];

    const int yr = blockIdx.x;  // grid1 row 0..27
    const int b  = blockIdx.y;  // batch
    const int t  = threadIdx.x;

    const float* g1b = g1 + (size_t)b * 2 * Nc;
    const float* g2b = g2 + (size_t)b * 2 * Nc;

    if (t == 0) {
        float d1y = g1b[29] - g1b[0];
        float d1x = g1b[Nc + 29] - g1b[Nc + 0];
        float bin1 = __fsqrt_rn(__fadd_rn(__fmul_rn(d1y, d1y), __fmul_rn(d1x, d1x)));
        float d2y = g2b[29] - g2b[0];
        float d2x = g2b[Nc + 29] - g2b[Nc + 0];
        float bin2 = __fsqrt_rn(__fadd_rn(__fmul_rn(d2y, d2y), __fmul_rn(d2x, d2x)));
        s_bin1 = bin1; s_bin2 = bin2;
        float g1y = g1b[yr * Wc];
        s_g1y = g1y;
        float thrm = 0.7f * fmaxf(bin1, bin2) * 1.0002f + 1e-3f;
        int r0 = -1, r1 = -2;
        for (int my = 0; my < Hc; my++) {
            float gy = g2b[my * Wc];
            if (fabsf(gy - g1y) <= thrm) { if (r0 < 0) r0 = my; r1 = my; }
        }
        int nb = r1 - r0 + 1;
        if (nb < 0) nb = 0;
        if (nb > BROWS) nb = BROWS;     // provably never clamps (see BROWS derivation)
        s_r0 = r0; s_nb = nb;
        s_np = 0;
    }
    __syncthreads();

    double acc0 = 0.0, acc1 = 0.0;   // per-thread sims
    int    cnt0 = 0,  cnt1 = 0;

    const int nb = s_nb;
    if (nb > 0) {                       // ---- active path ----
        const int r0 = s_r0;
        const int m0 = r0 * Wc;
        const int bandn = nb * Wc;      // <= 84, multiple of 28
        const int nqz = bandn >> 2;
        const int nbase = yr * Wc;

        // stage grid coords + zero norms
        if (t < Wc) s_g1x[t] = g1b[Nc + nbase + t];
        for (int j = t; j < bandn; j += 256) {
            s_g2y[j] = g2b[m0 + j];
            s_g2x[j] = g2b[Nc + m0 + j];
        }
        if (t < 2 * Wc) yn2[t / Wc][t % Wc] = 0.f;
        if (t < 2 * BN) zn2[t / BN][t % BN] = 0.f;
        __syncthreads();

        // ---- exact mask evaluation (bit-matches reference float ops) ----
        const float bin1 = s_bin1, bin2 = s_bin2, g1y = s_g1y;
        for (int idx = t; idx < Wc * bandn; idx += 256) {
            int nl = idx / bandn;
            int j  = idx - nl * bandn;
            float dy = g1y - s_g2y[j];
            float dx = s_g1x[nl] - s_g2x[j];
            float dist = __fsqrt_rn(__fadd_rn(__fmul_rn(dy, dy), __fmul_rn(dx, dx)));
            bool m1 = (__fdiv_rn(dist, bin1) <= 0.7f);
            bool m2 = (__fdiv_rn(dist, bin2) <= 0.7f);
            if (m1) { int p = atomicAdd(&s_np, 1); if (p < MAXP) s_pairs[p] = (0 << 16) | (nl << 8) | j; }
            if (m2) { int p = atomicAdd(&s_np, 1); if (p < MAXP) s_pairs[p] = (1 << 16) | (nl << 8) | j; }
        }
        __syncthreads();
        int np = s_np; if (np > MAXP) np = MAXP;

        // view 0: y1 vs z2 ; view 1: y2 vs z1
        const float* ya[2] = { y1 + (size_t)b * Cc * Nc, y2 + (size_t)b * Cc * Nc };
        const float* za[2] = { z2 + (size_t)b * Cc * Nc, z1 + (size_t)b * Cc * Nc };

        unsigned int ysm0 = (unsigned int)__cvta_generic_to_shared(ysm);
        unsigned int zsm0 = (unsigned int)__cvta_generic_to_shared(zsm);

        float dacc[2] = {0.f, 0.f};

        // ---- chunk loop ----
        for (int ci = 0; ci < NCHUNK; ci++) {
            const int cc = ci * CH;
            __syncthreads();   // previous chunk's readers done before refill
            for (int e = t; e < 2 * CH * (Wc / 4); e += 256) {     // 448 ops
                int v  = e / (CH * (Wc / 4));
                int r  = e - v * (CH * (Wc / 4));
                int cl = r / (Wc / 4);
                int q  = r - cl * (Wc / 4);
                unsigned int saddr = ysm0 + (unsigned int)(((v * CH + cl) * Wc + (q << 2)) * 4);
                cp_async16(saddr, ya[v] + (size_t)(cc + cl) * Nc + nbase + (q << 2));
            }
            for (int e = t; e < 2 * CH * nqz; e += 256) {          // <=1344 ops
                int v  = e / (CH * nqz);
                int r  = e - v * (CH * nqz);
                int cl = r / nqz;
                int q  = r - cl * nqz;
                unsigned int saddr = zsm0 + (unsigned int)((v * ZOFF1 + cl * BN + (q << 2)) * 4);
                cp_async16(saddr, za[v] + (size_t)(cc + cl) * Nc + m0 + (q << 2));
            }
            cp_async_commit_wait();
            __syncthreads();

            // column norms^2 (lanes: consecutive cols -> conflict-free)
            if (t < 2 * Wc) {
                int v = t / Wc, nl = t - v * Wc;
                const float* yv = ysm + v * CH * Wc;
                float s = 0.f;
                #pragma unroll
                for (int cl = 0; cl < CH; cl++) { float x = yv[cl * Wc + nl]; s += x * x; }
                yn2[v][nl] += s;
            }
            for (int col = t; col < 2 * bandn; col += 256) {
                int v = col / bandn, j = col - v * bandn;
                const float* zv = zsm + v * ZOFF1;
                float s = 0.f;
                #pragma unroll
                for (int cl = 0; cl < CH; cl++) { float x = zv[cl * BN + j]; s += x * x; }
                zn2[v][j] += s;
            }

            // balanced pair dots (all threads, <=2 pairs each)
            for (int p = t, k = 0; p < np; p += 256, k++) {
                int pr = s_pairs[p];
                int v = pr >> 16, nl = (pr >> 8) & 255, j = pr & 255;
                const float* yv = ysm + v * CH * Wc + nl;
                const float* zv = zsm + v * ZOFF1 + j;
                float s = 0.f;
                #pragma unroll
                for (int cl = 0; cl < CH; cl++) s = fmaf(yv[cl * Wc], zv[cl * BN], s);
                dacc[k] += s;
            }
        }
        __syncthreads();

        // ---- per-pair cosine sims ----
        for (int p = t, k = 0; p < np; p += 256, k++) {
            int pr = s_pairs[p];
            int v = pr >> 16, nl = (pr >> 8) & 255, j = pr & 255;
            float den = fmaxf(__fsqrt_rn(yn2[v][nl] * zn2[v][j]), 1e-8f);
            float sim = dacc[k] / den;
            if (v == 0) { acc0 += (double)sim; cnt0++; }
            else        { acc1 += (double)sim; cnt1++; }
        }
    }

    // ---- block reduction of sims ----
    for (int off = 16; off; off >>= 1) {
        acc0 += __shfl_down_sync(0xffffffffu, acc0, off);
        acc1 += __shfl_down_sync(0xffffffffu, acc1, off);
        cnt0 += __shfl_down_sync(0xffffffffu, cnt0, off);
        cnt1 += __shfl_down_sync(0xffffffffu, cnt1, off);
    }
    int wid = t >> 5, lane = t & 31;
    if (lane == 0) { red_s0[wid] = acc0; red_s1[wid] = acc1; red_c0[wid] = (double)cnt0; red_c1[wid] = (double)cnt1; }
    __syncthreads();

    // ---- accumulate into 4 global scalars (zero-init; fin resets) ----
    if (t == 0) {
        double S0 = 0, S1 = 0, C0 = 0, C1 = 0;
        #pragma unroll
        for (int w = 0; w < 8; w++) { S0 += red_s0[w]; S1 += red_s1[w]; C0 += red_c0[w]; C1 += red_c1[w]; }
        atomicAdd(&g_sum[0], S0);
        atomicAdd(&g_sum[1], S1);
        atomicAdd(&g_cnt[0], (unsigned long long)(long long)C0);
        atomicAdd(&g_cnt[1], (unsigned long long)(long long)C1);
    }
}

__global__ void cl_fin_kernel(float* __restrict__ out) {
    double l0 = g_cnt[0] ? g_sum[0] / (double)g_cnt[0] : 0.0;
    double l1 = g_cnt[1] ? g_sum[1] / (double)g_cnt[1] : 0.0;
    out[0] = (float)(-(l0 + l1));
    // reset for next graph replay (deterministic: every call starts from zeros)
    g_sum[0] = 0.0; g_sum[1] = 0.0;
    g_cnt[0] = 0ull; g_cnt[1] = 0ull;
}

extern "C" void kernel_launch(void* const* d_in, const int* in_sizes, int n_in,
                              void* d_out, int out_size) {
    (void)in_sizes; (void)n_in; (void)out_size;
    const float* y1 = (const float*)d_in[0];
    const float* y2 = (const float*)d_in[1];
    const float* z1 = (const float*)d_in[2];
    const float* z2 = (const float*)d_in[3];
    const float* g1 = (const float*)d_in[4];
    const float* g2 = (const float*)d_in[5];

    dim3 grid(Hc, Bc);
    cl_main_kernel<<<grid, 256>>>(y1, y2, z1, z2, g1, g2);
    cl_fin_kernel<<<1, 1>>>((float*)d_out);
}